// round 2
// baseline (speedup 1.0000x reference)
#include <cuda_runtime.h>

// Grouped shifted conv1d:
//   t = roll(x, +1, axis=3); patches = unfold(t, k=3, pad=1) along last axis
//   y[o,k,n,m] = sum_{i,j} patches[o*64+i, n, j, m] * W[i,k,j]
//   out = roll(y, +1, axis=2)  (H roll folded into store index)
//
// Grid: (56 input rows, 2 groups). Block: 224 threads = 56 m x 4 k-quads.

#define NTHREADS 224

__global__ void __launch_bounds__(NTHREADS)
shiftconv_kernel(const float* __restrict__ x,
                 const float* __restrict__ W,
                 float* __restrict__ out)
{
    const int n = blockIdx.x;   // input H row 0..55
    const int o = blockIdx.y;   // channel group 0..1

    // xs[i][u], u in [0,58): pre-rolled + zero-padded row slab.
    // xs[i][u] = x[o*64+i, n, (u-2) mod 56] for u in [1,56]; xs[i][0]=xs[i][57]=0.
    __shared__ float xs[64 * 58];
    // ws[i][j][k] so the 4 contiguous k's per thread load as one float4.
    __shared__ float ws[64 * 48];

    const int tid = threadIdx.x;

    // --- stage W: src layout (i,k,j) row-major -> dst [i][j][k] ---
    for (int t = tid; t < 64 * 48; t += NTHREADS) {
        const int k = t & 15;
        const int j = (t >> 4) % 3;
        const int i = t / 48;
        ws[t] = W[i * 48 + k * 3 + j];
    }

    // --- stage x slab, fusing the +1 circular roll and the zero pad ---
    const float* xg = x + (o * 64) * 56 * 56 + n * 56;
    for (int d = tid; d < 64 * 56; d += NTHREADS) {
        const int i   = d / 56;
        const int u   = (d % 56) + 1;       // 1..56
        const int src = (u + 54) % 56;      // (u-2) mod 56
        xs[i * 58 + u] = xg[i * 3136 + src];
    }
    if (tid < 128) {                        // zero both pad columns
        const int i = tid >> 1;
        xs[i * 58 + (tid & 1) * 57] = 0.0f;
    }
    __syncthreads();

    // --- compute: thread owns (m, k-quad), 4 accumulators ---
    const int m     = tid % 56;
    const int kq    = tid / 56;             // 0..3
    const int kbase = kq * 4;

    float acc0 = 0.f, acc1 = 0.f, acc2 = 0.f, acc3 = 0.f;

    #pragma unroll 8
    for (int i = 0; i < 64; ++i) {
        const float a = xs[i * 58 + m];         // tap j=0
        const float b = xs[i * 58 + m + 1];     // tap j=1
        const float c = xs[i * 58 + m + 2];     // tap j=2

        const float4 w0 = *reinterpret_cast<const float4*>(&ws[i * 48 +      kbase]);
        const float4 w1 = *reinterpret_cast<const float4*>(&ws[i * 48 + 16 + kbase]);
        const float4 w2 = *reinterpret_cast<const float4*>(&ws[i * 48 + 32 + kbase]);

        acc0 += a * w0.x + b * w1.x + c * w2.x;
        acc1 += a * w0.y + b * w1.y + c * w2.y;
        acc2 += a * w0.z + b * w1.z + c * w2.z;
        acc3 += a * w0.w + b * w1.w + c * w2.w;
    }

    // --- store with the output H-roll folded in: y_out[n+1] = y[n] ---
    const int n_out = (n + 1) % 56;
    float* og = out + ((o * 16 + kbase) * 56 + n_out) * 56 + m;
    og[0 * 56 * 56] = acc0;
    og[1 * 56 * 56] = acc1;
    og[2 * 56 * 56] = acc2;
    og[3 * 56 * 56] = acc3;
}

extern "C" void kernel_launch(void* const* d_in, const int* in_sizes, int n_in,
                              void* d_out, int out_size)
{
    const float* x = (const float*)d_in[0];   // (1,128,56,56) fp32
    const float* W = (const float*)d_in[1];   // (64,16,3) fp32
    float* out     = (float*)d_out;           // (1,32,56,56) fp32

    dim3 grid(56, 2);
    shiftconv_kernel<<<grid, NTHREADS>>>(x, W, out);
}

// round 3
// speedup vs baseline: 1.4388x; 1.4388x over previous
#include <cuda_runtime.h>

// Grouped shifted conv1d:
//   t = roll(x, +1, axis=3); patches = unfold(t, k=3, pad=1) along last axis
//   y[o,k,n,m] = sum_{i,j} patches[o*64+i, n, j, m] * W[i,k,j]
//   out = roll(y, +1, axis=2)  (H roll folded into store index)
//
// Grid: (56 input rows, 2 groups). Block: 896 threads = 56 m x 4 k-quads x 4 i-quarters.
// Each thread accumulates over 16 input channels; 4-way partials combined in smem.

#define NT 896

__global__ void __launch_bounds__(NT)
shiftconv_kernel(const float* __restrict__ x,
                 const float* __restrict__ W,
                 float* __restrict__ out)
{
    const int n = blockIdx.x;   // input H row 0..55
    const int o = blockIdx.y;   // channel group 0..1

    // xs[i][u], u in [0,58): pre-rolled + zero-padded row slab.
    __shared__ float  xs[64 * 58];
    // ws[i][j][k]: 4 contiguous k's per thread -> one LDS.128 (broadcast in-warp).
    __shared__ float  ws[64 * 48];
    // partial sums from i-quarters 1..3
    __shared__ float4 red[3 * 224];

    const int tid = threadIdx.x;
    const int m   = tid % 56;
    const int r   = tid / 56;      // 0..15
    const int kq  = r & 3;         // 0..3
    const int iq  = r >> 2;        // 0..3

    // --- stage W: src layout (i,k,j) row-major -> dst [i][j][k] ---
    #pragma unroll
    for (int t = tid; t < 64 * 48; t += NT) {
        const int k = t & 15;
        const int j = (t >> 4) % 3;
        const int i = t / 48;
        ws[t] = W[i * 48 + k * 3 + j];
    }

    // --- stage x slab, fusing the +1 circular roll and the zero pad ---
    // xs[i][m+1] = x[o*64+i, n, (m-1) mod 56]
    const float* xg  = x + (o * 64) * 3136 + n * 56;
    const int    src = (m + 55) % 56;
    #pragma unroll
    for (int it = 0; it < 4; ++it) {
        const int i = it * 16 + r;
        xs[i * 58 + m + 1] = xg[i * 3136 + src];
    }
    if (tid < 128)                          // zero both pad columns
        xs[(tid >> 1) * 58 + (tid & 1) * 57] = 0.0f;
    __syncthreads();

    // --- compute: thread owns (m, k-quad, i-quarter), 16-iter loop ---
    const int kbase = kq * 4;
    float acc0 = 0.f, acc1 = 0.f, acc2 = 0.f, acc3 = 0.f;

    const float* xsp = xs + iq * 16 * 58 + m;
    const float* wsp = ws + iq * 16 * 48 + kbase;

    #pragma unroll
    for (int i = 0; i < 16; ++i) {
        const float a = xsp[i * 58];        // tap j=0
        const float b = xsp[i * 58 + 1];    // tap j=1
        const float c = xsp[i * 58 + 2];    // tap j=2

        const float4 w0 = *reinterpret_cast<const float4*>(wsp + i * 48);
        const float4 w1 = *reinterpret_cast<const float4*>(wsp + i * 48 + 16);
        const float4 w2 = *reinterpret_cast<const float4*>(wsp + i * 48 + 32);

        acc0 += a * w0.x + b * w1.x + c * w2.x;
        acc1 += a * w0.y + b * w1.y + c * w2.y;
        acc2 += a * w0.z + b * w1.z + c * w2.z;
        acc3 += a * w0.w + b * w1.w + c * w2.w;
    }

    // --- 4-way partial reduction through smem ---
    const int part = kq * 56 + m;           // 0..223
    if (iq != 0)
        red[(iq - 1) * 224 + part] = make_float4(acc0, acc1, acc2, acc3);
    __syncthreads();

    if (iq == 0) {
        const float4 p0 = red[part];
        const float4 p1 = red[224 + part];
        const float4 p2 = red[448 + part];
        acc0 += p0.x + p1.x + p2.x;
        acc1 += p0.y + p1.y + p2.y;
        acc2 += p0.z + p1.z + p2.z;
        acc3 += p0.w + p1.w + p2.w;

        // store with the output H-roll folded in: y_out[n+1] = y[n]
        const int n_out = (n + 1) % 56;
        float* og = out + ((o * 16 + kbase) * 56 + n_out) * 56 + m;
        og[0 * 3136] = acc0;
        og[1 * 3136] = acc1;
        og[2 * 3136] = acc2;
        og[3 * 3136] = acc3;
    }
}

extern "C" void kernel_launch(void* const* d_in, const int* in_sizes, int n_in,
                              void* d_out, int out_size)
{
    const float* x = (const float*)d_in[0];   // (1,128,56,56) fp32
    const float* W = (const float*)d_in[1];   // (64,16,3) fp32
    float* out     = (float*)d_out;           // (1,32,56,56) fp32

    dim3 grid(56, 2);
    shiftconv_kernel<<<grid, NT>>>(x, W, out);
}